// round 1
// baseline (speedup 1.0000x reference)
#include <cuda_runtime.h>
#include <cstdint>
#include <cstddef>

#define DEVINL __device__ __forceinline__

constexpr int Bb   = 8;
constexpr int NSEQ = 1024;
constexpr int Dd   = 768;
constexpr int Hh   = 12;
constexpr int HD   = 64;
constexpr int Mrows = Bb * NSEQ;   // 8192

// ---------------- scratch (allocation-free rule: __device__ globals) ----------
__device__ float g_qh[(size_t)Bb * Hh * NSEQ * HD];   // [B,H,N,64]
__device__ float g_kh[(size_t)Bb * Hh * NSEQ * HD];
__device__ float g_vh[(size_t)Bb * Hh * NSEQ * HD];
__device__ float g_ao[(size_t)Mrows * Dd];            // attention out [B,N,D]

// ---------------- helpers ------------------------------------------------------
DEVINL uint32_t f2tf32(float x) {
    uint32_t r;
    asm("cvt.rna.tf32.f32 %0, %1;" : "=r"(r) : "f"(x));
    return r;
}

DEVINL void mma_tf32(float d[4], const uint32_t a[4], const uint32_t b[2], const float c[4]) {
    asm("mma.sync.aligned.m16n8k8.row.col.f32.tf32.tf32.f32 "
        "{%0,%1,%2,%3}, {%4,%5,%6,%7}, {%8,%9}, {%10,%11,%12,%13};"
        : "=f"(d[0]), "=f"(d[1]), "=f"(d[2]), "=f"(d[3])
        : "r"(a[0]), "r"(a[1]), "r"(a[2]), "r"(a[3]),
          "r"(b[0]), "r"(b[1]),
          "f"(c[0]), "f"(c[1]), "f"(c[2]), "f"(c[3]));
}

DEVINL void cp_async16(void* smem, const void* gmem) {
    uint32_t s = (uint32_t)__cvta_generic_to_shared(smem);
    asm volatile("cp.async.cg.shared.global [%0], [%1], 16;" :: "r"(s), "l"(gmem));
}
DEVINL void cp_commit() { asm volatile("cp.async.commit_group;"); }
template<int N> DEVINL void cp_wait() { asm volatile("cp.async.wait_group %0;" :: "n"(N)); }

// ================================================================================
// GEMM: out = A[M,768] @ W[768,768]^T + bias
//   MODE 0: epilogue scatters to [B,H,N,64] head layout
//   MODE 1: plain row-major [M,768]
// Tiles: BM=128, BN=128, BK=16, 256 threads (8 warps of 32x64), tf32 mma,
// cp.async 2-stage double buffering. Smem rows padded to 20 floats => conflict-free
// fragment LDS (stride 20: (lane/4)*20 + lane%4 mod 32 hits 32 distinct banks).
// ================================================================================
template<int MODE>
__global__ __launch_bounds__(256)
void gemm_xwT(const float* __restrict__ A, const float* __restrict__ W,
              const float* __restrict__ bias, float* __restrict__ out) {
    constexpr int BM = 128, BN = 128, BK = 16, LDA = 20;
    __shared__ float As[2][BM][LDA];
    __shared__ float Bs[2][BN][LDA];

    const int tid = threadIdx.x;
    const int m0 = blockIdx.y * BM;
    const int n0 = blockIdx.x * BN;

    const int srow = tid >> 1;          // 0..127
    const int scol = (tid & 1) * 8;     // 0 or 8

    const int wid = tid >> 5, lane = tid & 31;
    const int wm = wid >> 1, wn = wid & 1;          // warp tile: rows wm*32, cols wn*64
    const int g = lane >> 2, t = lane & 3;

    float acc[2][8][4];
#pragma unroll
    for (int i = 0; i < 2; i++)
#pragma unroll
        for (int j = 0; j < 8; j++)
#pragma unroll
            for (int q = 0; q < 4; q++) acc[i][j][q] = 0.f;

    auto stage = [&](int buf, int k0) {
        const float* ag = A + (size_t)(m0 + srow) * Dd + k0 + scol;
        cp_async16(&As[buf][srow][scol],     ag);
        cp_async16(&As[buf][srow][scol + 4], ag + 4);
        const float* bg = W + (size_t)(n0 + srow) * Dd + k0 + scol;
        cp_async16(&Bs[buf][srow][scol],     bg);
        cp_async16(&Bs[buf][srow][scol + 4], bg + 4);
        cp_commit();
    };

    constexpr int NK = Dd / BK;   // 48
    stage(0, 0);

    for (int kt = 0; kt < NK; kt++) {
        if (kt + 1 < NK) { stage((kt + 1) & 1, (kt + 1) * BK); cp_wait<1>(); }
        else             { cp_wait<0>(); }
        __syncthreads();
        const int s = kt & 1;
#pragma unroll
        for (int ks = 0; ks < 2; ks++) {
            uint32_t af[2][4], bf[8][2];
#pragma unroll
            for (int mt = 0; mt < 2; mt++) {
                const int rb = wm * 32 + mt * 16;
                af[mt][0] = f2tf32(As[s][rb + g    ][ks * 8 + t    ]);
                af[mt][1] = f2tf32(As[s][rb + g + 8][ks * 8 + t    ]);
                af[mt][2] = f2tf32(As[s][rb + g    ][ks * 8 + t + 4]);
                af[mt][3] = f2tf32(As[s][rb + g + 8][ks * 8 + t + 4]);
            }
#pragma unroll
            for (int nt = 0; nt < 8; nt++) {
                const int cb = wn * 64 + nt * 8;
                bf[nt][0] = f2tf32(Bs[s][cb + g][ks * 8 + t    ]);
                bf[nt][1] = f2tf32(Bs[s][cb + g][ks * 8 + t + 4]);
            }
#pragma unroll
            for (int mt = 0; mt < 2; mt++)
#pragma unroll
                for (int nt = 0; nt < 8; nt++)
                    mma_tf32(acc[mt][nt], af[mt], bf[nt], acc[mt][nt]);
        }
        __syncthreads();
    }

    // epilogue
#pragma unroll
    for (int mt = 0; mt < 2; mt++) {
#pragma unroll
        for (int nt = 0; nt < 8; nt++) {
#pragma unroll
            for (int jr = 0; jr < 2; jr++) {
                const int m = m0 + wm * 32 + mt * 16 + g + jr * 8;
                const int c = n0 + wn * 64 + nt * 8 + t * 2;
                const float v0 = acc[mt][nt][jr * 2 + 0] + bias[c];
                const float v1 = acc[mt][nt][jr * 2 + 1] + bias[c + 1];
                if (MODE == 0) {
                    const int b = m >> 10, ns = m & 1023;
                    const int h = c >> 6,  hd = c & 63;
                    float* o = out + ((size_t)((b * Hh + h) * NSEQ + ns)) * HD + hd;
                    o[0] = v0; o[1] = v1;
                } else {
                    float* o = out + (size_t)m * Dd + c;
                    o[0] = v0; o[1] = v1;
                }
            }
        }
    }
}

// ================================================================================
// Fused attention (flash-style, tf32 mma):
//   per block: one (b,h), 64 q-rows; 4 warps x 16 q-rows.
//   Loop over 8 k-tiles of 128: stage K/V/bias(+mask) -> S = Q@K^T + bias ->
//   online softmax -> P through smem -> O += P@V. Output to [B,N,D].
// Smem strides chosen for conflict-free fragment LDS:
//   Ks stride 68, Vs stride 72, Ps stride 132.
// ================================================================================
constexpr int LK = 68, LV = 72, LP = 132;
constexpr int SMEM_ATTN = (128 * LK + 128 * LV + 64 * LP) * 4;   // 105472 B

__global__ __launch_bounds__(128)
void attn_fused(const float* __restrict__ qh, const float* __restrict__ kh,
                const float* __restrict__ vh, const float* __restrict__ bias,
                const int* __restrict__ mask, float* __restrict__ out) {
    extern __shared__ float sm[];
    float* Ks = sm;                       // [128][68]
    float* Vs = sm + 128 * LK;            // [128][72]
    float* Ps = sm + 128 * LK + 128 * LV; // [64][132] (bias, then P; Q staging at start)

    const int tid = threadIdx.x;
    const int w = tid >> 5, lane = tid & 31;
    const int g = lane >> 2, t = lane & 3;
    const int qt = blockIdx.x;            // 0..15
    const int bh = blockIdx.y;            // 0..95
    const int b = bh / Hh;
    const int h = bh - b * Hh;
    const int q0 = qt * 64;

    // ---- stage Q tile (scaled by 1/sqrt(64)=0.125) into Ps area as [64][68]
    {
        const float4* qg = reinterpret_cast<const float4*>(qh + ((size_t)bh * NSEQ + q0) * HD);
#pragma unroll
        for (int i = 0; i < 8; i++) {
            const int idx = tid + i * 128;          // 0..1023
            const int r = idx >> 4, c4 = idx & 15;
            const float4 v = qg[idx];
            float* dst = Ps + r * LK + c4 * 4;
            dst[0] = v.x * 0.125f; dst[1] = v.y * 0.125f;
            dst[2] = v.z * 0.125f; dst[3] = v.w * 0.125f;
        }
    }
    __syncthreads();

    uint32_t qf[8][4];
#pragma unroll
    for (int ks = 0; ks < 8; ks++) {
        const int rb = w * 16;
        qf[ks][0] = f2tf32(Ps[(rb + g    ) * LK + ks * 8 + t    ]);
        qf[ks][1] = f2tf32(Ps[(rb + g + 8) * LK + ks * 8 + t    ]);
        qf[ks][2] = f2tf32(Ps[(rb + g    ) * LK + ks * 8 + t + 4]);
        qf[ks][3] = f2tf32(Ps[(rb + g + 8) * LK + ks * 8 + t + 4]);
    }
    __syncthreads();   // Ps about to be reused for bias

    float Of[8][4];
#pragma unroll
    for (int i = 0; i < 8; i++)
#pragma unroll
        for (int j = 0; j < 4; j++) Of[i][j] = 0.f;
    float m_lo = -INFINITY, m_hi = -INFINITY, l_lo = 0.f, l_hi = 0.f;

    const size_t kvbase = (size_t)bh * NSEQ * HD;

    for (int kt = 0; kt < 8; kt++) {
        const int k0 = kt * 128;
        // ---- stage K, V tiles [128][64]
        {
            const float4* kg = reinterpret_cast<const float4*>(kh + kvbase + (size_t)k0 * HD);
            const float4* vg = reinterpret_cast<const float4*>(vh + kvbase + (size_t)k0 * HD);
#pragma unroll
            for (int i = 0; i < 16; i++) {
                const int idx = tid + i * 128;       // 0..2047
                const int r = idx >> 4, c4 = idx & 15;
                const float4 kv = kg[idx];
                const float4 vv = vg[idx];
                float* kd = Ks + r * LK + c4 * 4;
                kd[0] = kv.x; kd[1] = kv.y; kd[2] = kv.z; kd[3] = kv.w;
                float* vd = Vs + r * LV + c4 * 4;
                vd[0] = vv.x; vd[1] = vv.y; vd[2] = vv.z; vd[3] = vv.w;
            }
            // ---- stage effective bias (bias + mask) [64][128] into Ps
            const float4* bg = reinterpret_cast<const float4*>(
                bias + ((size_t)bh * NSEQ + q0) * NSEQ + k0);
            const int4* mg = reinterpret_cast<const int4*>(
                mask + ((size_t)b * NSEQ + q0) * NSEQ + k0);
#pragma unroll
            for (int i = 0; i < 16; i++) {
                const int idx = tid + i * 128;       // 0..2047
                const int r = idx >> 5, c4 = idx & 31;
                const float4 bv = bg[r * (NSEQ / 4) + c4];
                const int4   mv = mg[r * (NSEQ / 4) + c4];
                float* pd = Ps + r * LP + c4 * 4;
                pd[0] = mv.x ? bv.x : -1e30f;
                pd[1] = mv.y ? bv.y : -1e30f;
                pd[2] = mv.z ? bv.z : -1e30f;
                pd[3] = mv.w ? bv.w : -1e30f;
            }
        }
        __syncthreads();

        // ---- S = Q @ K^T + bias  (16 rows x 128 cols per warp)
        float sacc[16][4];
#pragma unroll
        for (int nt = 0; nt < 16; nt++) {
            sacc[nt][0] = 0.f; sacc[nt][1] = 0.f; sacc[nt][2] = 0.f; sacc[nt][3] = 0.f;
        }
#pragma unroll
        for (int nt = 0; nt < 16; nt++) {
            const int cb = nt * 8;
#pragma unroll
            for (int ks = 0; ks < 8; ks++) {
                uint32_t bf[2];
                bf[0] = f2tf32(Ks[(cb + g) * LK + ks * 8 + t    ]);
                bf[1] = f2tf32(Ks[(cb + g) * LK + ks * 8 + t + 4]);
                mma_tf32(sacc[nt], qf[ks], bf, sacc[nt]);
            }
            const int r0 = w * 16 + g;
            sacc[nt][0] += Ps[ r0      * LP + cb + t * 2    ];
            sacc[nt][1] += Ps[ r0      * LP + cb + t * 2 + 1];
            sacc[nt][2] += Ps[(r0 + 8) * LP + cb + t * 2    ];
            sacc[nt][3] += Ps[(r0 + 8) * LP + cb + t * 2 + 1];
        }

        // ---- online softmax (2 rows per thread, 4-lane row groups)
        float mx_lo = -INFINITY, mx_hi = -INFINITY;
#pragma unroll
        for (int nt = 0; nt < 16; nt++) {
            mx_lo = fmaxf(mx_lo, fmaxf(sacc[nt][0], sacc[nt][1]));
            mx_hi = fmaxf(mx_hi, fmaxf(sacc[nt][2], sacc[nt][3]));
        }
        mx_lo = fmaxf(mx_lo, __shfl_xor_sync(0xffffffffu, mx_lo, 1));
        mx_lo = fmaxf(mx_lo, __shfl_xor_sync(0xffffffffu, mx_lo, 2));
        mx_hi = fmaxf(mx_hi, __shfl_xor_sync(0xffffffffu, mx_hi, 1));
        mx_hi = fmaxf(mx_hi, __shfl_xor_sync(0xffffffffu, mx_hi, 2));
        const float mn_lo = fmaxf(m_lo, mx_lo), mn_hi = fmaxf(m_hi, mx_hi);
        const float corr_lo = __expf(m_lo - mn_lo), corr_hi = __expf(m_hi - mn_hi);
        float sum_lo = 0.f, sum_hi = 0.f;
        const int r0 = w * 16 + g;
#pragma unroll
        for (int nt = 0; nt < 16; nt++) {
            const float p0 = __expf(sacc[nt][0] - mn_lo);
            const float p1 = __expf(sacc[nt][1] - mn_lo);
            const float p2 = __expf(sacc[nt][2] - mn_hi);
            const float p3 = __expf(sacc[nt][3] - mn_hi);
            sum_lo += p0 + p1; sum_hi += p2 + p3;
            Ps[ r0      * LP + nt * 8 + t * 2    ] = p0;
            Ps[ r0      * LP + nt * 8 + t * 2 + 1] = p1;
            Ps[(r0 + 8) * LP + nt * 8 + t * 2    ] = p2;
            Ps[(r0 + 8) * LP + nt * 8 + t * 2 + 1] = p3;
        }
        sum_lo += __shfl_xor_sync(0xffffffffu, sum_lo, 1);
        sum_lo += __shfl_xor_sync(0xffffffffu, sum_lo, 2);
        sum_hi += __shfl_xor_sync(0xffffffffu, sum_hi, 1);
        sum_hi += __shfl_xor_sync(0xffffffffu, sum_hi, 2);
        l_lo = l_lo * corr_lo + sum_lo;
        l_hi = l_hi * corr_hi + sum_hi;
        m_lo = mn_lo; m_hi = mn_hi;
#pragma unroll
        for (int nt2 = 0; nt2 < 8; nt2++) {
            Of[nt2][0] *= corr_lo; Of[nt2][1] *= corr_lo;
            Of[nt2][2] *= corr_hi; Of[nt2][3] *= corr_hi;
        }
        __syncwarp();

        // ---- O += P @ V  (16 x 64 per warp, K=128)
#pragma unroll
        for (int ks2 = 0; ks2 < 16; ks2++) {
            uint32_t af[4];
            const int rb = w * 16;
            af[0] = f2tf32(Ps[(rb + g    ) * LP + ks2 * 8 + t    ]);
            af[1] = f2tf32(Ps[(rb + g + 8) * LP + ks2 * 8 + t    ]);
            af[2] = f2tf32(Ps[(rb + g    ) * LP + ks2 * 8 + t + 4]);
            af[3] = f2tf32(Ps[(rb + g + 8) * LP + ks2 * 8 + t + 4]);
#pragma unroll
            for (int nt2 = 0; nt2 < 8; nt2++) {
                uint32_t bf[2];
                bf[0] = f2tf32(Vs[(ks2 * 8 + t    ) * LV + nt2 * 8 + g]);
                bf[1] = f2tf32(Vs[(ks2 * 8 + t + 4) * LV + nt2 * 8 + g]);
                mma_tf32(Of[nt2], af, bf, Of[nt2]);
            }
        }
        __syncthreads();
    }

    // ---- epilogue: normalize and write [B,N,D]
    const float il_lo = 1.f / l_lo, il_hi = 1.f / l_hi;
    float* ob = out + ((size_t)(b * NSEQ) + q0) * Dd + h * HD;
#pragma unroll
    for (int nt2 = 0; nt2 < 8; nt2++) {
        const int r = w * 16 + g;
        const int c = nt2 * 8 + t * 2;
        ob[(size_t)r * Dd + c    ]       = Of[nt2][0] * il_lo;
        ob[(size_t)r * Dd + c + 1]       = Of[nt2][1] * il_lo;
        ob[(size_t)(r + 8) * Dd + c    ] = Of[nt2][2] * il_hi;
        ob[(size_t)(r + 8) * Dd + c + 1] = Of[nt2][3] * il_hi;
    }
}

// ================================================================================
extern "C" void kernel_launch(void* const* d_in, const int* /*in_sizes*/, int /*n_in*/,
                              void* d_out, int /*out_size*/) {
    const float* q    = (const float*)d_in[0];
    const float* k    = (const float*)d_in[1];
    const float* v    = (const float*)d_in[2];
    const float* bias = (const float*)d_in[3];
    const int*   mask = (const int*)  d_in[4];
    const float* Wq   = (const float*)d_in[5];
    const float* bq   = (const float*)d_in[6];
    const float* Wk   = (const float*)d_in[7];
    const float* bk   = (const float*)d_in[8];
    const float* Wv   = (const float*)d_in[9];
    const float* bv   = (const float*)d_in[10];
    const float* Wo   = (const float*)d_in[11];
    const float* bo   = (const float*)d_in[12];

    float *pqh, *pkh, *pvh, *pao;
    cudaGetSymbolAddress((void**)&pqh, g_qh);
    cudaGetSymbolAddress((void**)&pkh, g_kh);
    cudaGetSymbolAddress((void**)&pvh, g_vh);
    cudaGetSymbolAddress((void**)&pao, g_ao);

    cudaFuncSetAttribute(attn_fused, cudaFuncAttributeMaxDynamicSharedMemorySize, SMEM_ATTN);

    const dim3 gg(Dd / 128, Mrows / 128);   // (6, 64)
    gemm_xwT<0><<<gg, 256>>>(q, Wq, bq, pqh);
    gemm_xwT<0><<<gg, 256>>>(k, Wk, bk, pkh);
    gemm_xwT<0><<<gg, 256>>>(v, Wv, bv, pvh);

    attn_fused<<<dim3(NSEQ / 64, Bb * Hh), 128, SMEM_ATTN>>>(pqh, pkh, pvh, bias, mask, pao);

    gemm_xwT<1><<<gg, 256>>>(pao, Wo, bo, (float*)d_out);
}

// round 3
// speedup vs baseline: 1.0519x; 1.0519x over previous
#include <cuda_runtime.h>
#include <cstdint>
#include <cstddef>

#define DEVINL __device__ __forceinline__

constexpr int Bb   = 8;
constexpr int NSEQ = 1024;
constexpr int Dd   = 768;
constexpr int Hh   = 12;
constexpr int HD   = 64;
constexpr int Mrows = Bb * NSEQ;   // 8192

// ---------------- scratch (allocation-free rule: __device__ globals) ----------
__device__ float g_qh[(size_t)Bb * Hh * NSEQ * HD];   // [B,H,N,64]
__device__ float g_kh[(size_t)Bb * Hh * NSEQ * HD];
__device__ float g_vh[(size_t)Bb * Hh * NSEQ * HD];
__device__ float g_ao[(size_t)Mrows * Dd];            // attention out [B,N,D]

// ---------------- helpers ------------------------------------------------------
DEVINL uint32_t f2tf32(float x) {
    uint32_t r;
    asm("cvt.rna.tf32.f32 %0, %1;" : "=r"(r) : "f"(x));
    return r;
}

DEVINL void mma_tf32(float d[4], const uint32_t a[4], const uint32_t b[2], const float c[4]) {
    asm("mma.sync.aligned.m16n8k8.row.col.f32.tf32.tf32.f32 "
        "{%0,%1,%2,%3}, {%4,%5,%6,%7}, {%8,%9}, {%10,%11,%12,%13};"
        : "=f"(d[0]), "=f"(d[1]), "=f"(d[2]), "=f"(d[3])
        : "r"(a[0]), "r"(a[1]), "r"(a[2]), "r"(a[3]),
          "r"(b[0]), "r"(b[1]),
          "f"(c[0]), "f"(c[1]), "f"(c[2]), "f"(c[3]));
}

DEVINL void cp_async16(void* smem, const void* gmem) {
    uint32_t s = (uint32_t)__cvta_generic_to_shared(smem);
    asm volatile("cp.async.cg.shared.global [%0], [%1], 16;" :: "r"(s), "l"(gmem));
}
DEVINL void cp_commit() { asm volatile("cp.async.commit_group;"); }
template<int N> DEVINL void cp_wait() { asm volatile("cp.async.wait_group %0;" :: "n"(N)); }

// ================================================================================
// GEMM: out = A[M,768] @ W[768,768]^T + bias
//   MODE 0: epilogue scatters to [B,H,N,64] head layout
//   MODE 1: plain row-major [M,768]
// BM=128, BN=128, BK=16, 256 threads (8 warps, 32x64 warp tiles), tf32 mma,
// 3-stage cp.async pipeline (dynamic smem), ONE __syncthreads per k-iter.
// ================================================================================
constexpr int G_LDA = 20;
constexpr int G_STAGE = 128 * G_LDA;                  // floats per matrix per stage
constexpr int SMEM_GEMM = 3 * 2 * G_STAGE * 4;        // 61440 B

template<int MODE>
__global__ __launch_bounds__(256)
void gemm_xwT(const float* __restrict__ A, const float* __restrict__ W,
              const float* __restrict__ bias, float* __restrict__ out) {
    constexpr int BM = 128, BN = 128, BK = 16, LDA = G_LDA, NK = Dd / BK;  // NK=48
    extern __shared__ float gsm[];
    // layout: As[3][128][LDA] then Bs[3][128][LDA]
    float* Asm = gsm;
    float* Bsm = gsm + 3 * G_STAGE;

    const int tid = threadIdx.x;
    const int m0 = blockIdx.y * BM;
    const int n0 = blockIdx.x * BN;

    const int srow = tid >> 1;          // 0..127
    const int scol = (tid & 1) * 8;     // 0 or 8

    const int wid = tid >> 5, lane = tid & 31;
    const int wm = wid >> 1, wn = wid & 1;          // warp tile: rows wm*32, cols wn*64
    const int g = lane >> 2, t = lane & 3;

    float acc[2][8][4] = {};

    auto stage = [&](int buf, int k0) {
        float* As = Asm + buf * G_STAGE;
        float* Bs = Bsm + buf * G_STAGE;
        const float* ag = A + (size_t)(m0 + srow) * Dd + k0 + scol;
        cp_async16(As + srow * LDA + scol,     ag);
        cp_async16(As + srow * LDA + scol + 4, ag + 4);
        const float* bg = W + (size_t)(n0 + srow) * Dd + k0 + scol;
        cp_async16(Bs + srow * LDA + scol,     bg);
        cp_async16(Bs + srow * LDA + scol + 4, bg + 4);
        cp_commit();
    };

    stage(0, 0);
    stage(1, BK);

    for (int kt = 0; kt < NK; kt++) {
        if (kt + 1 < NK) cp_wait<1>(); else cp_wait<0>();
        __syncthreads();
        if (kt + 2 < NK) stage((kt + 2) % 3, (kt + 2) * BK);
        const int s = kt % 3;
        const float* As = Asm + s * G_STAGE;
        const float* Bs = Bsm + s * G_STAGE;
#pragma unroll
        for (int ks = 0; ks < 2; ks++) {
            uint32_t af[2][4], bf[8][2];
#pragma unroll
            for (int mt = 0; mt < 2; mt++) {
                const int rb = wm * 32 + mt * 16;
                af[mt][0] = f2tf32(As[(rb + g    ) * LDA + ks * 8 + t    ]);
                af[mt][1] = f2tf32(As[(rb + g + 8) * LDA + ks * 8 + t    ]);
                af[mt][2] = f2tf32(As[(rb + g    ) * LDA + ks * 8 + t + 4]);
                af[mt][3] = f2tf32(As[(rb + g + 8) * LDA + ks * 8 + t + 4]);
            }
#pragma unroll
            for (int nt = 0; nt < 8; nt++) {
                const int cb = wn * 64 + nt * 8;
                bf[nt][0] = f2tf32(Bs[(cb + g) * LDA + ks * 8 + t    ]);
                bf[nt][1] = f2tf32(Bs[(cb + g) * LDA + ks * 8 + t + 4]);
            }
#pragma unroll
            for (int mt = 0; mt < 2; mt++)
#pragma unroll
                for (int nt = 0; nt < 8; nt++)
                    mma_tf32(acc[mt][nt], af[mt], bf[nt], acc[mt][nt]);
        }
    }

    // epilogue
#pragma unroll
    for (int mt = 0; mt < 2; mt++) {
#pragma unroll
        for (int nt = 0; nt < 8; nt++) {
#pragma unroll
            for (int jr = 0; jr < 2; jr++) {
                const int m = m0 + wm * 32 + mt * 16 + g + jr * 8;
                const int c = n0 + wn * 64 + nt * 8 + t * 2;
                const float v0 = acc[mt][nt][jr * 2 + 0] + bias[c];
                const float v1 = acc[mt][nt][jr * 2 + 1] + bias[c + 1];
                if (MODE == 0) {
                    const int b = m >> 10, ns = m & 1023;
                    const int h = c >> 6,  hd = c & 63;
                    float* o = out + ((size_t)((b * Hh + h) * NSEQ + ns)) * HD + hd;
                    o[0] = v0; o[1] = v1;
                } else {
                    float* o = out + (size_t)m * Dd + c;
                    o[0] = v0; o[1] = v1;
                }
            }
        }
    }
}

// ================================================================================
// Fused attention (flash-style, tf32 mma), pipelined:
//   block = 256 threads (8 warps), q-tile = 128 rows (16 per warp), k-tile = 64.
//   cp.async DOUBLE-BUFFERED staging of K, V, bias, mask; one __syncthreads/tile.
//   S = Q@K^T + bias (masked) -> online softmax -> P via smem -> O += P@V.
// Smem strides: K/bias/P stride 68 (conflict-free frag LDS), V stride 72.
// ================================================================================
constexpr int LK = 68, LV = 72, LP = 68;
constexpr int SM_K = 2 * 64 * LK;     // floats
constexpr int SM_V = 2 * 64 * LV;
constexpr int SM_B = 2 * 128 * LP;
constexpr int SM_M = 2 * 128 * LP;    // ints
constexpr int SMEM_ATTN = (SM_K + SM_V + SM_B + SM_M) * 4;   // 210944 B

__global__ __launch_bounds__(256, 1)
void attn_fused(const float* __restrict__ qh, const float* __restrict__ kh,
                const float* __restrict__ vh, const float* __restrict__ bias,
                const int* __restrict__ mask, float* __restrict__ out) {
    extern __shared__ float sm[];
    float* Ks  = sm;                  // [2][64][LK]
    float* Vs  = sm + SM_K;           // [2][64][LV]
    float* Bsm = Vs + SM_V;           // [2][128][LP]  bias then P
    int*   Msm = (int*)(Bsm + SM_B);  // [2][128][LP]
    float* Qst = Bsm + 128 * LP;      // Q staging in Bsm buffer 1 (freed before tile 1)

    const int tid = threadIdx.x;
    const int w = tid >> 5, lane = tid & 31;
    const int g = lane >> 2, t = lane & 3;
    const int rb = w * 16;
    const int qt = blockIdx.x;        // 0..7
    const int bh = blockIdx.y;        // 0..95
    const int b = bh / Hh;
    const int h = bh - b * Hh;
    const int q0 = qt * 128;
    const size_t kvbase = (size_t)bh * NSEQ * HD;

    auto stage = [&](int buf, int kt) {
        const int k0 = kt * 64;
        const float* kg = kh + kvbase + (size_t)k0 * HD;
        const float* vg = vh + kvbase + (size_t)k0 * HD;
#pragma unroll
        for (int i = 0; i < 4; i++) {
            const int c = tid + i * 256;            // 0..1023
            const int r = c >> 4, c4 = c & 15;
            cp_async16(Ks + buf * 64 * LK + r * LK + c4 * 4, kg + r * HD + c4 * 4);
            cp_async16(Vs + buf * 64 * LV + r * LV + c4 * 4, vg + r * HD + c4 * 4);
        }
        const float* bg = bias + ((size_t)bh * NSEQ + q0) * NSEQ + k0;
        const int*   mg = mask + ((size_t)b * NSEQ + q0) * NSEQ + k0;
#pragma unroll
        for (int i = 0; i < 8; i++) {
            const int c = tid + i * 256;            // 0..2047
            const int r = c >> 4, c4 = c & 15;
            cp_async16(Bsm + buf * 128 * LP + r * LP + c4 * 4, bg + (size_t)r * NSEQ + c4 * 4);
            cp_async16(Msm + buf * 128 * LP + r * LP + c4 * 4, mg + (size_t)r * NSEQ + c4 * 4);
        }
        cp_commit();
    };

    stage(0, 0);   // first tile in flight behind Q setup

    // ---- stage Q tile (scaled by 1/8) into Qst
    {
        const float4* qg = reinterpret_cast<const float4*>(qh + ((size_t)bh * NSEQ + q0) * HD);
#pragma unroll
        for (int i = 0; i < 8; i++) {
            const int idx = tid + i * 256;          // 0..2047
            const int r = idx >> 4, c4 = idx & 15;
            const float4 v = qg[idx];
            float* dst = Qst + r * LP + c4 * 4;
            dst[0] = v.x * 0.125f; dst[1] = v.y * 0.125f;
            dst[2] = v.z * 0.125f; dst[3] = v.w * 0.125f;
        }
    }
    __syncthreads();

    uint32_t qf[8][4];
#pragma unroll
    for (int ks = 0; ks < 8; ks++) {
        qf[ks][0] = f2tf32(Qst[(rb + g    ) * LP + ks * 8 + t    ]);
        qf[ks][1] = f2tf32(Qst[(rb + g + 8) * LP + ks * 8 + t    ]);
        qf[ks][2] = f2tf32(Qst[(rb + g    ) * LP + ks * 8 + t + 4]);
        qf[ks][3] = f2tf32(Qst[(rb + g + 8) * LP + ks * 8 + t + 4]);
    }

    float Of[8][4] = {};
    float m_lo = -INFINITY, m_hi = -INFINITY, l_lo = 0.f, l_hi = 0.f;

    for (int kt = 0; kt < 16; kt++) {
        const int buf = kt & 1;
        cp_wait<0>();
        __syncthreads();                       // tile kt visible; all done with kt-1
        if (kt + 1 < 16) stage(buf ^ 1, kt + 1);   // prefetch behind compute

        float* Kb  = Ks  + buf * 64 * LK;
        float* Vb  = Vs  + buf * 64 * LV;
        float* Bb2 = Bsm + buf * 128 * LP;
        int*   Mb  = Msm + buf * 128 * LP;

        // ---- S = Q @ K^T, then +bias / mask
        float sacc[8][4] = {};
#pragma unroll
        for (int nt = 0; nt < 8; nt++) {
            const int cb = nt * 8;
#pragma unroll
            for (int ks = 0; ks < 8; ks++) {
                uint32_t bf[2];
                bf[0] = f2tf32(Kb[(cb + g) * LK + ks * 8 + t    ]);
                bf[1] = f2tf32(Kb[(cb + g) * LK + ks * 8 + t + 4]);
                mma_tf32(sacc[nt], qf[ks], bf, sacc[nt]);
            }
            const int r0 = rb + g;
            const int c = cb + t * 2;
            const int m0i = Mb[ r0      * LP + c    ];
            const int m1i = Mb[ r0      * LP + c + 1];
            const int m2i = Mb[(r0 + 8) * LP + c    ];
            const int m3i = Mb[(r0 + 8) * LP + c + 1];
            sacc[nt][0] = m0i ? sacc[nt][0] + Bb2[ r0      * LP + c    ] : -1e30f;
            sacc[nt][1] = m1i ? sacc[nt][1] + Bb2[ r0      * LP + c + 1] : -1e30f;
            sacc[nt][2] = m2i ? sacc[nt][2] + Bb2[(r0 + 8) * LP + c    ] : -1e30f;
            sacc[nt][3] = m3i ? sacc[nt][3] + Bb2[(r0 + 8) * LP + c + 1] : -1e30f;
        }

        // ---- online softmax (rows in 4-lane groups)
        float mx_lo = -INFINITY, mx_hi = -INFINITY;
#pragma unroll
        for (int nt = 0; nt < 8; nt++) {
            mx_lo = fmaxf(mx_lo, fmaxf(sacc[nt][0], sacc[nt][1]));
            mx_hi = fmaxf(mx_hi, fmaxf(sacc[nt][2], sacc[nt][3]));
        }
        mx_lo = fmaxf(mx_lo, __shfl_xor_sync(0xffffffffu, mx_lo, 1));
        mx_lo = fmaxf(mx_lo, __shfl_xor_sync(0xffffffffu, mx_lo, 2));
        mx_hi = fmaxf(mx_hi, __shfl_xor_sync(0xffffffffu, mx_hi, 1));
        mx_hi = fmaxf(mx_hi, __shfl_xor_sync(0xffffffffu, mx_hi, 2));
        const float mn_lo = fmaxf(m_lo, mx_lo), mn_hi = fmaxf(m_hi, mx_hi);
        const float corr_lo = __expf(m_lo - mn_lo), corr_hi = __expf(m_hi - mn_hi);
        float sum_lo = 0.f, sum_hi = 0.f;
        const int r0 = rb + g;
#pragma unroll
        for (int nt = 0; nt < 8; nt++) {
            const float p0 = __expf(sacc[nt][0] - mn_lo);
            const float p1 = __expf(sacc[nt][1] - mn_lo);
            const float p2 = __expf(sacc[nt][2] - mn_hi);
            const float p3 = __expf(sacc[nt][3] - mn_hi);
            sum_lo += p0 + p1; sum_hi += p2 + p3;
            Bb2[ r0      * LP + nt * 8 + t * 2    ] = p0;
            Bb2[ r0      * LP + nt * 8 + t * 2 + 1] = p1;
            Bb2[(r0 + 8) * LP + nt * 8 + t * 2    ] = p2;
            Bb2[(r0 + 8) * LP + nt * 8 + t * 2 + 1] = p3;
        }
        sum_lo += __shfl_xor_sync(0xffffffffu, sum_lo, 1);
        sum_lo += __shfl_xor_sync(0xffffffffu, sum_lo, 2);
        sum_hi += __shfl_xor_sync(0xffffffffu, sum_hi, 1);
        sum_hi += __shfl_xor_sync(0xffffffffu, sum_hi, 2);
        l_lo = l_lo * corr_lo + sum_lo;
        l_hi = l_hi * corr_hi + sum_hi;
        m_lo = mn_lo; m_hi = mn_hi;
#pragma unroll
        for (int n2 = 0; n2 < 8; n2++) {
            Of[n2][0] *= corr_lo; Of[n2][1] *= corr_lo;
            Of[n2][2] *= corr_hi; Of[n2][3] *= corr_hi;
        }
        __syncwarp();   // P stores visible within warp before fragment loads

        // ---- O += P @ V  (16 x 64 per warp, K=64)
#pragma unroll
        for (int ks2 = 0; ks2 < 8; ks2++) {
            uint32_t af[4];
            af[0] = f2tf32(Bb2[(rb + g    ) * LP + ks2 * 8 + t    ]);
            af[1] = f2tf32(Bb2[(rb + g + 8) * LP + ks2 * 8 + t    ]);
            af[2] = f2tf32(Bb2[(rb + g    ) * LP + ks2 * 8 + t + 4]);
            af[3] = f2tf32(Bb2[(rb + g + 8) * LP + ks2 * 8 + t + 4]);
#pragma unroll
            for (int n2 = 0; n2 < 8; n2++) {
                uint32_t bf[2];
                bf[0] = f2tf32(Vb[(ks2 * 8 + t    ) * LV + n2 * 8 + g]);
                bf[1] = f2tf32(Vb[(ks2 * 8 + t + 4) * LV + n2 * 8 + g]);
                mma_tf32(Of[n2], af, bf, Of[n2]);
            }
        }
    }

    // ---- epilogue: normalize and write [B,N,D]
    const float il_lo = 1.f / l_lo, il_hi = 1.f / l_hi;
    float* ob = out + ((size_t)(b * NSEQ) + q0) * Dd + h * HD;
#pragma unroll
    for (int n2 = 0; n2 < 8; n2++) {
        const int r = rb + g;
        const int c = n2 * 8 + t * 2;
        ob[(size_t)r * Dd + c    ]       = Of[n2][0] * il_lo;
        ob[(size_t)r * Dd + c + 1]       = Of[n2][1] * il_lo;
        ob[(size_t)(r + 8) * Dd + c    ] = Of[n2][2] * il_hi;
        ob[(size_t)(r + 8) * Dd + c + 1] = Of[n2][3] * il_hi;
    }
}

// ================================================================================
extern "C" void kernel_launch(void* const* d_in, const int* /*in_sizes*/, int /*n_in*/,
                              void* d_out, int /*out_size*/) {
    const float* q    = (const float*)d_in[0];
    const float* k    = (const float*)d_in[1];
    const float* v    = (const float*)d_in[2];
    const float* bias = (const float*)d_in[3];
    const int*   mask = (const int*)  d_in[4];
    const float* Wq   = (const float*)d_in[5];
    const float* bq   = (const float*)d_in[6];
    const float* Wk   = (const float*)d_in[7];
    const float* bk   = (const float*)d_in[8];
    const float* Wv   = (const float*)d_in[9];
    const float* bv   = (const float*)d_in[10];
    const float* Wo   = (const float*)d_in[11];
    const float* bo   = (const float*)d_in[12];

    float *pqh, *pkh, *pvh, *pao;
    cudaGetSymbolAddress((void**)&pqh, g_qh);
    cudaGetSymbolAddress((void**)&pkh, g_kh);
    cudaGetSymbolAddress((void**)&pvh, g_vh);
    cudaGetSymbolAddress((void**)&pao, g_ao);

    cudaFuncSetAttribute(gemm_xwT<0>, cudaFuncAttributeMaxDynamicSharedMemorySize, SMEM_GEMM);
    cudaFuncSetAttribute(gemm_xwT<1>, cudaFuncAttributeMaxDynamicSharedMemorySize, SMEM_GEMM);
    cudaFuncSetAttribute(attn_fused, cudaFuncAttributeMaxDynamicSharedMemorySize, SMEM_ATTN);

    const dim3 gg(Dd / 128, Mrows / 128);   // (6, 64)
    gemm_xwT<0><<<gg, 256, SMEM_GEMM>>>(q, Wq, bq, pqh);
    gemm_xwT<0><<<gg, 256, SMEM_GEMM>>>(k, Wk, bk, pkh);
    gemm_xwT<0><<<gg, 256, SMEM_GEMM>>>(v, Wv, bv, pvh);

    attn_fused<<<dim3(NSEQ / 128, Bb * Hh), 256, SMEM_ATTN>>>(pqh, pkh, pvh, bias, mask, pao);

    gemm_xwT<1><<<gg, 256, SMEM_GEMM>>>(pao, Wo, bo, (float*)d_out);
}